// round 3
// baseline (speedup 1.0000x reference)
#include <cuda_runtime.h>
#include <math.h>

#define B_  2
#define L_  2048
#define E_  1024
#define H_  16
#define DH  64

// Scratch: Q/K/V in [B*H, L, DH] layout (attention-friendly, contiguous per head)
__device__ float g_q[B_*H_*L_*DH];
__device__ float g_k[B_*H_*L_*DH];
__device__ float g_v[B_*H_*L_*DH];

// ---------------------------------------------------------------------------
// Projection GEMM:  Y[m,n] = sum_k X[m,k] * W[n,k] + bias[n]   (GEMM-NT)
// M=4096, N=1024, K=1024. Tile 128x128x8, 256 threads, 8x8 microtile.
// Output scattered into [B*H, L, DH] layout.
// blockIdx.z selects which of the three projections (q/k/v) this CTA computes.
// ---------------------------------------------------------------------------
__global__ __launch_bounds__(256) void proj_kernel(
    const float* __restrict__ xq, const float* __restrict__ xk, const float* __restrict__ xv,
    const float* __restrict__ wq, const float* __restrict__ wk, const float* __restrict__ wv,
    const float* __restrict__ bq, const float* __restrict__ bk, const float* __restrict__ bv)
{
    const float* X; const float* W; const float* Bias; float* Y;
    if (blockIdx.z == 0)      { X = xq; W = wq; Bias = bq; Y = g_q; }
    else if (blockIdx.z == 1) { X = xk; W = wk; Bias = bk; Y = g_k; }
    else                      { X = xv; W = wv; Bias = bv; Y = g_v; }

    __shared__ float As[8][128];   // As[kk][m]
    __shared__ float Ws[8][128];   // Ws[kk][n]

    const int tx = threadIdx.x & 15;   // 0..15 -> n microtile
    const int ty = threadIdx.x >> 4;   // 0..15 -> m microtile
    const int m0 = blockIdx.y * 128;
    const int n0 = blockIdx.x * 128;

    // global loader mapping: 256 threads load 128 rows x 8 cols (1 float4 each)
    const int ldr = threadIdx.x >> 1;        // 0..127
    const int ldc = (threadIdx.x & 1) * 4;   // 0 or 4
    const float* Ap = X + (size_t)(m0 + ldr) * E_ + ldc;
    const float* Wp = W + (size_t)(n0 + ldr) * E_ + ldc;

    float acc[8][8];
    #pragma unroll
    for (int i = 0; i < 8; i++)
        #pragma unroll
        for (int j = 0; j < 8; j++) acc[i][j] = 0.f;

    for (int k0 = 0; k0 < E_; k0 += 8) {
        float4 a = *reinterpret_cast<const float4*>(Ap + k0);
        float4 w = *reinterpret_cast<const float4*>(Wp + k0);
        __syncthreads();  // previous tile fully consumed
        As[ldc + 0][ldr] = a.x; As[ldc + 1][ldr] = a.y;
        As[ldc + 2][ldr] = a.z; As[ldc + 3][ldr] = a.w;
        Ws[ldc + 0][ldr] = w.x; Ws[ldc + 1][ldr] = w.y;
        Ws[ldc + 2][ldr] = w.z; Ws[ldc + 3][ldr] = w.w;
        __syncthreads();

        #pragma unroll
        for (int kk = 0; kk < 8; kk++) {
            float4 a0 = *reinterpret_cast<const float4*>(&As[kk][ty * 8]);
            float4 a1 = *reinterpret_cast<const float4*>(&As[kk][ty * 8 + 4]);
            float4 w0 = *reinterpret_cast<const float4*>(&Ws[kk][tx * 8]);
            float4 w1 = *reinterpret_cast<const float4*>(&Ws[kk][tx * 8 + 4]);
            float af[8] = {a0.x, a0.y, a0.z, a0.w, a1.x, a1.y, a1.z, a1.w};
            float wf[8] = {w0.x, w0.y, w0.z, w0.w, w1.x, w1.y, w1.z, w1.w};
            #pragma unroll
            for (int i = 0; i < 8; i++)
                #pragma unroll
                for (int j = 0; j < 8; j++)
                    acc[i][j] = fmaf(af[i], wf[j], acc[i][j]);
        }
    }

    // epilogue: add bias, scatter into [B*H, L, DH]
    const int ncol = n0 + tx * 8;          // 8 contiguous cols, all in one head
    const int h    = ncol >> 6;
    const int d0   = ncol & 63;
    const int b    = m0 >> 11;             // whole 128-row block within one batch
    const int lbase = (m0 & (L_ - 1)) + ty * 8;

    float bias0 = Bias[ncol + 0], bias1 = Bias[ncol + 1], bias2 = Bias[ncol + 2], bias3 = Bias[ncol + 3];
    float bias4 = Bias[ncol + 4], bias5 = Bias[ncol + 5], bias6 = Bias[ncol + 6], bias7 = Bias[ncol + 7];

    #pragma unroll
    for (int i = 0; i < 8; i++) {
        const int l = lbase + i;
        float* yp = Y + (((size_t)(b * H_ + h) * L_ + l) * DH + d0);
        float4 v0 = make_float4(acc[i][0] + bias0, acc[i][1] + bias1,
                                acc[i][2] + bias2, acc[i][3] + bias3);
        float4 v1 = make_float4(acc[i][4] + bias4, acc[i][5] + bias5,
                                acc[i][6] + bias6, acc[i][7] + bias7);
        *reinterpret_cast<float4*>(yp)     = v0;
        *reinterpret_cast<float4*>(yp + 4) = v1;
    }
}

// ---------------------------------------------------------------------------
// Flash attention, fp32. One thread = one query row; CTA = 64 query rows of
// one (b,h). K/V staged in 64x64 smem blocks; all inner-loop smem reads are
// warp-broadcast LDS.128 (conflict-free). Online softmax per 8-key chunk.
// grid = (L/64, B*H), block = 64.
// ---------------------------------------------------------------------------
__global__ __launch_bounds__(64) void attn_kernel(float* __restrict__ out)
{
    __shared__ float4 Ks[64 * 16];   // [j][d4]
    __shared__ float4 Vs[64 * 16];

    const int tid = threadIdx.x;
    const int bh  = blockIdx.y;
    const int b   = bh >> 4;
    const int h   = bh & 15;
    const int l   = blockIdx.x * 64 + tid;

    const float scale = 0.125f;  // 1/sqrt(64)

    // load this thread's query row (pre-scaled)
    const float4* qrow = reinterpret_cast<const float4*>(g_q + ((size_t)bh * L_ + l) * DH);
    float4 q4[16];
    #pragma unroll
    for (int d4 = 0; d4 < 16; d4++) {
        float4 t = qrow[d4];
        q4[d4] = make_float4(t.x * scale, t.y * scale, t.z * scale, t.w * scale);
    }

    float4 o4[16];
    #pragma unroll
    for (int d4 = 0; d4 < 16; d4++) o4[d4] = make_float4(0.f, 0.f, 0.f, 0.f);
    float mrun = -1e30f;
    float lsum = 0.f;

    const float4* kg = reinterpret_cast<const float4*>(g_k + (size_t)bh * L_ * DH);
    const float4* vg = reinterpret_cast<const float4*>(g_v + (size_t)bh * L_ * DH);

    for (int s0 = 0; s0 < L_; s0 += 64) {
        __syncthreads();
        const int base = s0 * 16;  // float4 index of block start
        #pragma unroll
        for (int i = 0; i < 16; i++) {
            int idx = tid + i * 64;
            Ks[idx] = kg[base + idx];
            Vs[idx] = vg[base + idx];
        }
        __syncthreads();

        #pragma unroll 1
        for (int jc = 0; jc < 64; jc += 8) {
            float sc[8];
            #pragma unroll
            for (int jj = 0; jj < 8; jj++) {
                const float4* kr = &Ks[(jc + jj) * 16];
                float a = 0.f;
                #pragma unroll
                for (int d4 = 0; d4 < 16; d4++) {
                    float4 kv = kr[d4];
                    a = fmaf(q4[d4].x, kv.x, a);
                    a = fmaf(q4[d4].y, kv.y, a);
                    a = fmaf(q4[d4].z, kv.z, a);
                    a = fmaf(q4[d4].w, kv.w, a);
                }
                sc[jj] = a;
            }
            float cmax = sc[0];
            #pragma unroll
            for (int jj = 1; jj < 8; jj++) cmax = fmaxf(cmax, sc[jj]);
            float nm = fmaxf(mrun, cmax);
            float corr = __expf(mrun - nm);
            mrun = nm;
            lsum *= corr;
            #pragma unroll
            for (int d4 = 0; d4 < 16; d4++) {
                o4[d4].x *= corr; o4[d4].y *= corr;
                o4[d4].z *= corr; o4[d4].w *= corr;
            }
            #pragma unroll
            for (int jj = 0; jj < 8; jj++) {
                float p = __expf(sc[jj] - mrun);
                lsum += p;
                const float4* vr = &Vs[(jc + jj) * 16];
                #pragma unroll
                for (int d4 = 0; d4 < 16; d4++) {
                    float4 vv = vr[d4];
                    o4[d4].x = fmaf(p, vv.x, o4[d4].x);
                    o4[d4].y = fmaf(p, vv.y, o4[d4].y);
                    o4[d4].z = fmaf(p, vv.z, o4[d4].z);
                    o4[d4].w = fmaf(p, vv.w, o4[d4].w);
                }
            }
        }
    }

    const float inv = 1.f / lsum;
    float* op = out + ((size_t)(b * L_ + l) * E_) + h * DH;
    #pragma unroll
    for (int d4 = 0; d4 < 16; d4++) {
        float4 r = make_float4(o4[d4].x * inv, o4[d4].y * inv,
                               o4[d4].z * inv, o4[d4].w * inv);
        *reinterpret_cast<float4*>(op + d4 * 4) = r;
    }
}

extern "C" void kernel_launch(void* const* d_in, const int* in_sizes, int n_in,
                              void* d_out, int out_size)
{
    const float* query = (const float*)d_in[0];
    const float* key   = (const float*)d_in[1];
    const float* value = (const float*)d_in[2];
    const float* wq    = (const float*)d_in[3];
    const float* bq    = (const float*)d_in[4];
    const float* wk    = (const float*)d_in[5];
    const float* bk    = (const float*)d_in[6];
    const float* wv    = (const float*)d_in[7];
    const float* bv    = (const float*)d_in[8];
    float* out = (float*)d_out;

    dim3 gproj(E_ / 128, (B_ * L_) / 128, 3);   // 8 x 32 x 3
    proj_kernel<<<gproj, 256>>>(query, key, value, wq, wk, wv, bq, bk, bv);

    dim3 gattn(L_ / 64, B_ * H_);               // 32 x 32
    attn_kernel<<<gattn, 64>>>(out);
}

// round 5
// speedup vs baseline: 1.0222x; 1.0222x over previous
#include <cuda_runtime.h>
#include <math.h>

#define B_  2
#define L_  2048
#define E_  1024
#define H_  16
#define DH  64

typedef unsigned long long u64;

__device__ float g_q[B_*H_*L_*DH];
__device__ float g_k[B_*H_*L_*DH];
__device__ float g_v[B_*H_*L_*DH];

// ---- packed f32x2 helpers (sm_103a FFMA2 — only reachable via explicit PTX) ----
__device__ __forceinline__ u64 pack2(float x, float y) {
    u64 r; asm("mov.b64 %0, {%1, %2};" : "=l"(r) : "f"(x), "f"(y)); return r;
}
__device__ __forceinline__ float2 unpack2(u64 v) {
    float2 r; asm("mov.b64 {%0, %1}, %2;" : "=f"(r.x), "=f"(r.y) : "l"(v)); return r;
}
__device__ __forceinline__ u64 fma2_(u64 a, u64 b, u64 c) {
    u64 d; asm("fma.rn.f32x2 %0, %1, %2, %3;" : "=l"(d) : "l"(a), "l"(b), "l"(c)); return d;
}
__device__ __forceinline__ u64 mul2_(u64 a, u64 b) {
    u64 d; asm("mul.rn.f32x2 %0, %1, %2;" : "=l"(d) : "l"(a), "l"(b)); return d;
}

// ---------------------------------------------------------------------------
// Projection GEMM (NT): Y[m,n] = X[m,:]·W[n,:] + bias[n]
// M=4096, N=1024, K=1024. 128x128x8 tile, 256 threads, 8x8 microtile,
// fma.rn.f32x2 inner product (32 FFMA2/kk instead of 64 FFMA).
// ---------------------------------------------------------------------------
__global__ __launch_bounds__(256) void proj_kernel(
    const float* __restrict__ xq, const float* __restrict__ xk, const float* __restrict__ xv,
    const float* __restrict__ wq, const float* __restrict__ wk, const float* __restrict__ wv,
    const float* __restrict__ bq, const float* __restrict__ bk, const float* __restrict__ bv)
{
    const float* X; const float* W; const float* Bias; float* Y;
    if (blockIdx.z == 0)      { X = xq; W = wq; Bias = bq; Y = g_q; }
    else if (blockIdx.z == 1) { X = xk; W = wk; Bias = bk; Y = g_k; }
    else                      { X = xv; W = wv; Bias = bv; Y = g_v; }

    __shared__ float As[8][128];
    __shared__ float Ws[8][128];

    const int tx = threadIdx.x & 15;
    const int ty = threadIdx.x >> 4;
    const int m0 = blockIdx.y * 128;
    const int n0 = blockIdx.x * 128;

    const int ldr = threadIdx.x >> 1;
    const int ldc = (threadIdx.x & 1) * 4;
    const float* Ap = X + (size_t)(m0 + ldr) * E_ + ldc;
    const float* Wp = W + (size_t)(n0 + ldr) * E_ + ldc;

    u64 acc2[8][4];
    #pragma unroll
    for (int i = 0; i < 8; i++)
        #pragma unroll
        for (int j = 0; j < 4; j++) acc2[i][j] = 0ull;

    for (int k0 = 0; k0 < E_; k0 += 8) {
        float4 a = *reinterpret_cast<const float4*>(Ap + k0);
        float4 w = *reinterpret_cast<const float4*>(Wp + k0);
        __syncthreads();
        As[ldc + 0][ldr] = a.x; As[ldc + 1][ldr] = a.y;
        As[ldc + 2][ldr] = a.z; As[ldc + 3][ldr] = a.w;
        Ws[ldc + 0][ldr] = w.x; Ws[ldc + 1][ldr] = w.y;
        Ws[ldc + 2][ldr] = w.z; Ws[ldc + 3][ldr] = w.w;
        __syncthreads();

        #pragma unroll
        for (int kk = 0; kk < 8; kk++) {
            float4 a0 = *reinterpret_cast<const float4*>(&As[kk][ty * 8]);
            float4 a1 = *reinterpret_cast<const float4*>(&As[kk][ty * 8 + 4]);
            const ulonglong2* wp2 = reinterpret_cast<const ulonglong2*>(&Ws[kk][tx * 8]);
            ulonglong2 wA = wp2[0];
            ulonglong2 wB = wp2[1];
            u64 wf2[4] = {wA.x, wA.y, wB.x, wB.y};
            float af[8] = {a0.x, a0.y, a0.z, a0.w, a1.x, a1.y, a1.z, a1.w};
            #pragma unroll
            for (int i = 0; i < 8; i++) {
                u64 a2 = pack2(af[i], af[i]);
                #pragma unroll
                for (int j = 0; j < 4; j++)
                    acc2[i][j] = fma2_(a2, wf2[j], acc2[i][j]);
            }
        }
    }

    const int ncol = n0 + tx * 8;
    const int h    = ncol >> 6;
    const int d0   = ncol & 63;
    const int b    = m0 >> 11;
    const int lbase = (m0 & (L_ - 1)) + ty * 8;

    float bias[8];
    #pragma unroll
    for (int j = 0; j < 8; j++) bias[j] = Bias[ncol + j];

    #pragma unroll
    for (int i = 0; i < 8; i++) {
        const int l = lbase + i;
        float* yp = Y + (((size_t)(b * H_ + h) * L_ + l) * DH + d0);
        float2 p0 = unpack2(acc2[i][0]);
        float2 p1 = unpack2(acc2[i][1]);
        float2 p2 = unpack2(acc2[i][2]);
        float2 p3 = unpack2(acc2[i][3]);
        float4 v0 = make_float4(p0.x + bias[0], p0.y + bias[1], p1.x + bias[2], p1.y + bias[3]);
        float4 v1 = make_float4(p2.x + bias[4], p2.y + bias[5], p3.x + bias[6], p3.y + bias[7]);
        *reinterpret_cast<float4*>(yp)     = v0;
        *reinterpret_cast<float4*>(yp + 4) = v1;
    }
}

// ---------------------------------------------------------------------------
// Flash attention, fp32, f32x2 inner loops. 1 thread = 1 query row,
// CTA = 64 query rows of one (b,h); K/V in 64x64 smem tiles (16 KB each).
// Row = 16 ulonglong2 chunks; chunk c holds float pairs (2c, 2c+1).
// Per key: 32 LDS.128 (broadcast) + 64 FFMA2 (was 128 FFMA).
// grid = (L/64, B*H), block = 64.
// ---------------------------------------------------------------------------
__global__ __launch_bounds__(64) void attn_kernel(float* __restrict__ out)
{
    __shared__ ulonglong2 Ks[64 * 16];
    __shared__ ulonglong2 Vs[64 * 16];

    const int tid = threadIdx.x;
    const int bh  = blockIdx.y;
    const int b   = bh >> 4;
    const int h   = bh & 15;
    const int l   = blockIdx.x * 64 + tid;

    const float scale = 0.125f;  // 1/sqrt(64)

    const float4* qrow = reinterpret_cast<const float4*>(g_q + ((size_t)bh * L_ + l) * DH);
    u64 q2[32];
    #pragma unroll
    for (int d4 = 0; d4 < 16; d4++) {
        float4 t = qrow[d4];
        q2[2*d4 + 0] = pack2(t.x * scale, t.y * scale);
        q2[2*d4 + 1] = pack2(t.z * scale, t.w * scale);
    }

    u64 o2[32];
    #pragma unroll
    for (int d2 = 0; d2 < 32; d2++) o2[d2] = 0ull;
    float mrun = -1e30f;
    float lsum = 0.f;

    const ulonglong2* kg = reinterpret_cast<const ulonglong2*>(g_k + (size_t)bh * L_ * DH);
    const ulonglong2* vg = reinterpret_cast<const ulonglong2*>(g_v + (size_t)bh * L_ * DH);

    for (int s0 = 0; s0 < L_; s0 += 64) {
        __syncthreads();
        const int base = s0 * 16;   // ulonglong2 index of tile start
        #pragma unroll
        for (int i = 0; i < 16; i++) {
            int idx = tid + i * 64;
            Ks[idx] = kg[base + idx];
            Vs[idx] = vg[base + idx];
        }
        __syncthreads();

        #pragma unroll 1
        for (int jc = 0; jc < 64; jc += 8) {
            float sc[8];
            #pragma unroll
            for (int jj = 0; jj < 8; jj++) {
                const ulonglong2* kr = &Ks[(jc + jj) * 16];
                u64 acc = 0ull;
                #pragma unroll
                for (int c = 0; c < 16; c++) {
                    ulonglong2 kv = kr[c];              // LDS.128 broadcast
                    acc = fma2_(q2[2*c + 0], kv.x, acc);
                    acc = fma2_(q2[2*c + 1], kv.y, acc);
                }
                float2 s2 = unpack2(acc);
                sc[jj] = s2.x + s2.y;
            }
            float cmax = sc[0];
            #pragma unroll
            for (int jj = 1; jj < 8; jj++) cmax = fmaxf(cmax, sc[jj]);
            float nm = fmaxf(mrun, cmax);
            float corr = __expf(mrun - nm);
            mrun = nm;
            lsum *= corr;
            u64 c2 = pack2(corr, corr);
            #pragma unroll
            for (int d2 = 0; d2 < 32; d2++) o2[d2] = mul2_(o2[d2], c2);
            #pragma unroll
            for (int jj = 0; jj < 8; jj++) {
                float p = __expf(sc[jj] - mrun);
                lsum += p;
                u64 p2 = pack2(p, p);
                const ulonglong2* vr = &Vs[(jc + jj) * 16];
                #pragma unroll
                for (int c = 0; c < 16; c++) {
                    ulonglong2 vv = vr[c];              // LDS.128 broadcast
                    o2[2*c + 0] = fma2_(p2, vv.x, o2[2*c + 0]);
                    o2[2*c + 1] = fma2_(p2, vv.y, o2[2*c + 1]);
                }
            }
        }
    }

    const float inv = 1.f / lsum;
    const u64 inv2 = pack2(inv, inv);
    float* op = out + ((size_t)(b * L_ + l) * E_) + h * DH;
    #pragma unroll
    for (int g = 0; g < 8; g++) {
        float2 rl = unpack2(mul2_(o2[4*g + 0], inv2));
        float2 rh = unpack2(mul2_(o2[4*g + 1], inv2));
        float2 r2 = unpack2(mul2_(o2[4*g + 2], inv2));
        float2 r3 = unpack2(mul2_(o2[4*g + 3], inv2));
        *reinterpret_cast<float4*>(op + g * 8)     = make_float4(rl.x, rl.y, rh.x, rh.y);
        *reinterpret_cast<float4*>(op + g * 8 + 4) = make_float4(r2.x, r2.y, r3.x, r3.y);
    }
}

extern "C" void kernel_launch(void* const* d_in, const int* in_sizes, int n_in,
                              void* d_out, int out_size)
{
    const float* query = (const float*)d_in[0];
    const float* key   = (const float*)d_in[1];
    const float* value = (const float*)d_in[2];
    const float* wq    = (const float*)d_in[3];
    const float* bq    = (const float*)d_in[4];
    const float* wk    = (const float*)d_in[5];
    const float* bk    = (const float*)d_in[6];
    const float* wv    = (const float*)d_in[7];
    const float* bv    = (const float*)d_in[8];
    float* out = (float*)d_out;

    dim3 gproj(E_ / 128, (B_ * L_) / 128, 3);
    proj_kernel<<<gproj, 256>>>(query, key, value, wq, wk, wv, bq, bk, bv);

    dim3 gattn(L_ / 64, B_ * H_);
    attn_kernel<<<gattn, 64>>>(out);
}